// round 2
// baseline (speedup 1.0000x reference)
#include <cuda_runtime.h>
#include <math.h>

// Problem constants
#define B_ROWS 16384
#define NCLS   1000
#define FDIM   768
#define TEMP_INV 10.0f   // 1/TEMP
#define CE_W   1.0f
#define SDC_W  0.1f
#define MOM    0.9f
#define EPSI   1e-8f

// GEMM tiling
#define MT 128
#define NT 128
#define KT 16
#define NKT (FDIM / KT)   // 48
#define LDA 132           // padded row length (keeps 16B alignment, breaks store conflicts)

// -------- device scratch (no dynamic allocation allowed) --------
__device__ float g_sumexp[B_ROWS];     // per-row sum of exp(sims/T)
__device__ float g_slabel[B_ROWS];     // sims[b, label[b]]
__device__ float g_w[B_ROWS];          // resp[b, label[b]]
__device__ float g_wsum[NCLS];         // per-class sum of w
__device__ float g_update[NCLS * FDIM];
__device__ float g_lce[1024];
__device__ float g_lsdc[1024];

// -------------------- init: zero accumulators --------------------
__global__ void k_init() {
    int i = blockIdx.x * blockDim.x + threadIdx.x;
    if (i < NCLS * FDIM) g_update[i] = 0.f;
    if (i < B_ROWS) g_sumexp[i] = 0.f;
    if (i < NCLS) g_wsum[i] = 0.f;
    if (i < 1024) { g_lce[i] = 0.f; g_lsdc[i] = 0.f; }
}

// -------------------- CE loss: one row per block --------------------
__global__ void k_ce(const float* __restrict__ out, const int* __restrict__ labels) {
    const int b = blockIdx.x;
    const float* row = out + (size_t)b * NCLS;
    const int tid = threadIdx.x;   // 256 threads

    __shared__ float sh[32];

    // --- max reduce ---
    float mx = -3.4e38f;
    for (int c = tid; c < NCLS; c += 256) mx = fmaxf(mx, row[c]);
    #pragma unroll
    for (int o = 16; o; o >>= 1) mx = fmaxf(mx, __shfl_xor_sync(0xffffffffu, mx, o));
    if ((tid & 31) == 0) sh[tid >> 5] = mx;
    __syncthreads();
    if (tid < 32) {
        float v = (tid < 8) ? sh[tid] : -3.4e38f;
        #pragma unroll
        for (int o = 16; o; o >>= 1) v = fmaxf(v, __shfl_xor_sync(0xffffffffu, v, o));
        if (tid == 0) sh[0] = v;
    }
    __syncthreads();
    mx = sh[0];
    __syncthreads();

    // --- sum exp(x - max) ---
    float s = 0.f;
    for (int c = tid; c < NCLS; c += 256) s += __expf(row[c] - mx);
    #pragma unroll
    for (int o = 16; o; o >>= 1) s += __shfl_xor_sync(0xffffffffu, s, o);
    if ((tid & 31) == 0) sh[tid >> 5] = s;
    __syncthreads();
    if (tid < 32) {
        float v = (tid < 8) ? sh[tid] : 0.f;
        #pragma unroll
        for (int o = 16; o; o >>= 1) v += __shfl_xor_sync(0xffffffffu, v, o);
        if (tid == 0) {
            float term = mx + logf(v) - row[labels[b]];
            atomicAdd(&g_lce[b & 1023], term);
        }
    }
}

// ------- fused sims GEMM + online softmax-denominator epilogue -------
// sims = features @ centers^T ; epilogue accumulates sum(exp(sims/T)) per row
// and captures sims[b, label[b]]. resp is never materialized.
__global__ __launch_bounds__(256, 2)
void k_gemm(const float* __restrict__ F, const float* __restrict__ Cn,
            const int* __restrict__ labels) {
    __shared__ float As[2][KT][LDA];
    __shared__ float Bs[2][KT][LDA];
    __shared__ float red[MT][17];

    const int tid = threadIdx.x;
    const int m0 = blockIdx.x * MT;
    const int n0 = blockIdx.y * NT;
    const int tx = tid & 15;
    const int ty = tid >> 4;

    // global-load slots: 512 float4 per (128x16) tile, 2 per thread
    const int l0r = tid >> 2;            // rows 0..63
    const int l1r = l0r + 64;            // rows 64..127
    const int lf  = (tid & 3) * 4;       // k-offset within tile (0,4,8,12)

    float acc[8][8];
    #pragma unroll
    for (int i = 0; i < 8; ++i)
        #pragma unroll
        for (int j = 0; j < 8; ++j) acc[i][j] = 0.f;

    const float4 z4 = make_float4(0.f, 0.f, 0.f, 0.f);
    const int c0 = n0 + l0r, c1 = n0 + l1r;

    // ---- load tile 0 into buffer 0 ----
    {
        float4 a0 = *(const float4*)(F + (size_t)(m0 + l0r) * FDIM + lf);
        float4 a1 = *(const float4*)(F + (size_t)(m0 + l1r) * FDIM + lf);
        float4 b0 = (c0 < NCLS) ? *(const float4*)(Cn + (size_t)c0 * FDIM + lf) : z4;
        float4 b1 = (c1 < NCLS) ? *(const float4*)(Cn + (size_t)c1 * FDIM + lf) : z4;
        As[0][lf+0][l0r]=a0.x; As[0][lf+1][l0r]=a0.y; As[0][lf+2][l0r]=a0.z; As[0][lf+3][l0r]=a0.w;
        As[0][lf+0][l1r]=a1.x; As[0][lf+1][l1r]=a1.y; As[0][lf+2][l1r]=a1.z; As[0][lf+3][l1r]=a1.w;
        Bs[0][lf+0][l0r]=b0.x; Bs[0][lf+1][l0r]=b0.y; Bs[0][lf+2][l0r]=b0.z; Bs[0][lf+3][l0r]=b0.w;
        Bs[0][lf+0][l1r]=b1.x; Bs[0][lf+1][l1r]=b1.y; Bs[0][lf+2][l1r]=b1.z; Bs[0][lf+3][l1r]=b1.w;
    }
    __syncthreads();

    for (int kt = 0; kt < NKT; ++kt) {
        const int buf = kt & 1;
        const bool more = (kt + 1 < NKT);
        float4 pa0, pa1, pb0, pb1;
        if (more) {
            const int kk = (kt + 1) * KT + lf;
            pa0 = *(const float4*)(F + (size_t)(m0 + l0r) * FDIM + kk);
            pa1 = *(const float4*)(F + (size_t)(m0 + l1r) * FDIM + kk);
            pb0 = (c0 < NCLS) ? *(const float4*)(Cn + (size_t)c0 * FDIM + kk) : z4;
            pb1 = (c1 < NCLS) ? *(const float4*)(Cn + (size_t)c1 * FDIM + kk) : z4;
        }
        #pragma unroll
        for (int k = 0; k < KT; ++k) {
            float a[8], b[8];
            *(float4*)&a[0] = *(const float4*)&As[buf][k][ty * 8];
            *(float4*)&a[4] = *(const float4*)&As[buf][k][ty * 8 + 4];
            *(float4*)&b[0] = *(const float4*)&Bs[buf][k][tx * 8];
            *(float4*)&b[4] = *(const float4*)&Bs[buf][k][tx * 8 + 4];
            #pragma unroll
            for (int i = 0; i < 8; ++i)
                #pragma unroll
                for (int j = 0; j < 8; ++j) acc[i][j] = fmaf(a[i], b[j], acc[i][j]);
        }
        if (more) {
            const int nb = buf ^ 1;
            As[nb][lf+0][l0r]=pa0.x; As[nb][lf+1][l0r]=pa0.y; As[nb][lf+2][l0r]=pa0.z; As[nb][lf+3][l0r]=pa0.w;
            As[nb][lf+0][l1r]=pa1.x; As[nb][lf+1][l1r]=pa1.y; As[nb][lf+2][l1r]=pa1.z; As[nb][lf+3][l1r]=pa1.w;
            Bs[nb][lf+0][l0r]=pb0.x; Bs[nb][lf+1][l0r]=pb0.y; Bs[nb][lf+2][l0r]=pb0.z; Bs[nb][lf+3][l0r]=pb0.w;
            Bs[nb][lf+0][l1r]=pb1.x; Bs[nb][lf+1][l1r]=pb1.y; Bs[nb][lf+2][l1r]=pb1.z; Bs[nb][lf+3][l1r]=pb1.w;
            __syncthreads();
        }
    }

    // ---- epilogue: per-row partial sum of exp(sims/T), capture label sim ----
    int lbs[8];
    #pragma unroll
    for (int i = 0; i < 8; ++i) lbs[i] = labels[m0 + ty * 8 + i];

    #pragma unroll
    for (int i = 0; i < 8; ++i) {
        float s = 0.f;
        #pragma unroll
        for (int j = 0; j < 8; ++j) {
            const int c = n0 + tx * 8 + j;
            if (c < NCLS) {
                s += __expf(acc[i][j] * TEMP_INV);
                if (c == lbs[i]) g_slabel[m0 + ty * 8 + i] = acc[i][j];
            }
        }
        red[ty * 8 + i][tx] = s;
    }
    __syncthreads();
    if (tid < MT) {
        float s = 0.f;
        #pragma unroll
        for (int t = 0; t < 16; ++t) s += red[tid][t];
        atomicAdd(&g_sumexp[m0 + tid], s);
    }
}

// -------- per-sample responsibility at label, wsum, SDC loss --------
__global__ void k_wsum(const int* __restrict__ labels) {
    int b = blockIdx.x * blockDim.x + threadIdx.x;
    if (b < B_ROWS) {
        float p = __expf(g_slabel[b] * TEMP_INV) / g_sumexp[b];
        g_w[b] = p;
        atomicAdd(&g_wsum[labels[b]], p);
        atomicAdd(&g_lsdc[b & 1023], -logf(p + EPSI));
    }
}

// -------- masked-weighted scatter: center_update accumulation --------
__global__ void k_scatter(const float* __restrict__ F, const int* __restrict__ labels) {
    const int b = blockIdx.x;
    const int lb = labels[b];
    const float coef = g_w[b] / (g_wsum[lb] + EPSI);
    float* dst = g_update + (size_t)lb * FDIM;
    const float* src = F + (size_t)b * FDIM;
    for (int d = threadIdx.x; d < FDIM; d += blockDim.x)
        atomicAdd(&dst[d], src[d] * coef);
}

// -------------------- loss finalize --------------------
__global__ void k_loss(float* __restrict__ d_out) {
    const int tid = threadIdx.x;  // 1024 threads
    __shared__ float s1[32], s2[32];
    float v1 = g_lce[tid];
    float v2 = g_lsdc[tid];
    #pragma unroll
    for (int o = 16; o; o >>= 1) {
        v1 += __shfl_xor_sync(0xffffffffu, v1, o);
        v2 += __shfl_xor_sync(0xffffffffu, v2, o);
    }
    if ((tid & 31) == 0) { s1[tid >> 5] = v1; s2[tid >> 5] = v2; }
    __syncthreads();
    if (tid < 32) {
        v1 = s1[tid]; v2 = s2[tid];
        #pragma unroll
        for (int o = 16; o; o >>= 1) {
            v1 += __shfl_xor_sync(0xffffffffu, v1, o);
            v2 += __shfl_xor_sync(0xffffffffu, v2, o);
        }
        if (tid == 0)
            d_out[0] = CE_W * v1 / (float)B_ROWS + SDC_W * v2 / (float)B_ROWS;
    }
}

// -------------------- centers finalize --------------------
__global__ void k_final(const float* __restrict__ centers, float* __restrict__ d_out) {
    int i = blockIdx.x * blockDim.x + threadIdx.x;
    if (i < NCLS * FDIM) {
        const int c = i / FDIM;
        const float w = g_wsum[c];
        d_out[1 + i] = (w > 0.f) ? (MOM * centers[i] + (1.f - MOM) * g_update[i])
                                 : centers[i];
    }
}

extern "C" void kernel_launch(void* const* d_in, const int* in_sizes, int n_in,
                              void* d_out, int out_size) {
    const float* outputs  = (const float*)d_in[0];
    const int*   labels   = (const int*)d_in[1];
    const float* features = (const float*)d_in[2];
    const float* centers  = (const float*)d_in[3];
    float* out = (float*)d_out;

    k_init<<<(NCLS * FDIM + 255) / 256, 256>>>();
    k_ce<<<B_ROWS, 256>>>(outputs, labels);
    {
        dim3 grid(B_ROWS / MT, (NCLS + NT - 1) / NT);  // 128 x 8
        k_gemm<<<grid, 256>>>(features, centers, labels);
    }
    k_wsum<<<(B_ROWS + 255) / 256, 256>>>(labels);
    k_scatter<<<B_ROWS, 256>>>(features, labels);
    k_loss<<<1, 1024>>>(out);
    k_final<<<(NCLS * FDIM + 255) / 256, 256>>>(centers, out);
}

// round 4
// speedup vs baseline: 2.3349x; 2.3349x over previous
#include <cuda_runtime.h>
#include <cuda_bf16.h>
#include <cstdint>
#include <math.h>

// ---------------- problem constants ----------------
#define B_ROWS 16384
#define NCLS   1000
#define FDIM   768
#define TEMP_INV 10.0f
#define CE_W   1.0f
#define SDC_W  0.1f
#define MOM    0.9f
#define EPSI   1e-8f

// ---------------- GEMM tiling ----------------
#define MT 128
#define NT 128
#define KC 64                      // k elems per chunk
#define NCHUNK (FDIM / KC)         // 12
#define TILE_B 16384               // one 128x64 bf16 tile (128B rows)
#define SMEM_DYN (4 * TILE_B + 1024)   // Ahi Alo Bhi Blo + align slack

// ---------------- device scratch ----------------
__device__ float g_sumexp[B_ROWS];
__device__ float g_slabel[B_ROWS];
__device__ float g_w[B_ROWS];
__device__ float g_wsum[NCLS];
__device__ float g_update[NCLS * FDIM];
__device__ float g_lce[1024];
__device__ float g_lsdc[1024];

// ---------------- helpers ----------------
__device__ __forceinline__ uint32_t smem_to_u32(const void* p) {
    uint32_t a;
    asm("{ .reg .u64 t; cvta.to.shared.u64 t, %1; cvt.u32.u64 %0, t; }" : "=r"(a) : "l"(p));
    return a;
}
#define SWZ128(off) ((off) ^ (((off) >> 3) & 0x70))

__device__ __forceinline__ void ldsm4(uint32_t* r, uint32_t addr) {
    asm volatile("ldmatrix.sync.aligned.m8n8.x4.shared.b16 {%0,%1,%2,%3}, [%4];"
        : "=r"(r[0]), "=r"(r[1]), "=r"(r[2]), "=r"(r[3]) : "r"(addr));
}
__device__ __forceinline__ void mma_bf16(float* d, const uint32_t* a, const uint32_t* b) {
    asm volatile("mma.sync.aligned.m16n8k16.row.col.f32.bf16.bf16.f32 "
        "{%0,%1,%2,%3}, {%4,%5,%6,%7}, {%8,%9}, {%0,%1,%2,%3};"
        : "+f"(d[0]), "+f"(d[1]), "+f"(d[2]), "+f"(d[3])
        : "r"(a[0]), "r"(a[1]), "r"(a[2]), "r"(a[3]), "r"(b[0]), "r"(b[1]));
}

// split 8 fp32 -> 4 b32 of packed bf16 hi + 4 of lo
__device__ __forceinline__ void split8(const float* xs, uint32_t* hw, uint32_t* lw) {
    #pragma unroll
    for (int i = 0; i < 4; ++i) {
        __nv_bfloat16 h0 = __float2bfloat16_rn(xs[2*i]);
        __nv_bfloat16 h1 = __float2bfloat16_rn(xs[2*i+1]);
        __nv_bfloat16 l0 = __float2bfloat16_rn(xs[2*i]   - __bfloat162float(h0));
        __nv_bfloat16 l1 = __float2bfloat16_rn(xs[2*i+1] - __bfloat162float(h1));
        hw[i] = (uint32_t)__bfloat16_as_ushort(h0) | ((uint32_t)__bfloat16_as_ushort(h1) << 16);
        lw[i] = (uint32_t)__bfloat16_as_ushort(l0) | ((uint32_t)__bfloat16_as_ushort(l1) << 16);
    }
}

// ---------------- init ----------------
__global__ void k_init() {
    int i = blockIdx.x * blockDim.x + threadIdx.x;
    if (i < NCLS * FDIM) g_update[i] = 0.f;
    if (i < B_ROWS) g_sumexp[i] = 0.f;
    if (i < NCLS) g_wsum[i] = 0.f;
    if (i < 1024) { g_lce[i] = 0.f; g_lsdc[i] = 0.f; }
}

// ---------------- CE loss: single-pass, register-resident row ----------------
__global__ __launch_bounds__(256) void k_ce(const float* __restrict__ out,
                                            const int* __restrict__ labels) {
    const int b = blockIdx.x;
    const float* row = out + (size_t)b * NCLS;
    const int tid = threadIdx.x;
    __shared__ float sh[32];
    __shared__ float shmx;

    float4 x = make_float4(-3.4e38f, -3.4e38f, -3.4e38f, -3.4e38f);
    const bool act = (tid < NCLS / 4);
    if (act) x = *(const float4*)(row + tid * 4);

    float mx = fmaxf(fmaxf(x.x, x.y), fmaxf(x.z, x.w));
    #pragma unroll
    for (int o = 16; o; o >>= 1) mx = fmaxf(mx, __shfl_xor_sync(0xffffffffu, mx, o));
    if ((tid & 31) == 0) sh[tid >> 5] = mx;
    __syncthreads();
    if (tid < 32) {
        float v = (tid < 8) ? sh[tid] : -3.4e38f;
        #pragma unroll
        for (int o = 4; o; o >>= 1) v = fmaxf(v, __shfl_xor_sync(0xffffffffu, v, o));
        if (tid == 0) shmx = v;
    }
    __syncthreads();
    mx = shmx;

    const int lb = labels[b];
    float s = 0.f, lval = 0.f;
    if (act) {
        s = __expf(x.x - mx) + __expf(x.y - mx) + __expf(x.z - mx) + __expf(x.w - mx);
        if (tid == (lb >> 2)) {
            const float* xe = &x.x;
            lval = xe[lb & 3];
        }
    }
    #pragma unroll
    for (int o = 16; o; o >>= 1) {
        s += __shfl_xor_sync(0xffffffffu, s, o);
        lval += __shfl_xor_sync(0xffffffffu, lval, o);
    }
    if ((tid & 31) == 0) { sh[tid >> 5] = s; sh[16 + (tid >> 5)] = lval; }
    __syncthreads();
    if (tid < 32) {
        float v = (tid < 8) ? sh[tid] : 0.f;
        float l = (tid < 8) ? sh[16 + tid] : 0.f;
        #pragma unroll
        for (int o = 4; o; o >>= 1) {
            v += __shfl_xor_sync(0xffffffffu, v, o);
            l += __shfl_xor_sync(0xffffffffu, l, o);
        }
        if (tid == 0) atomicAdd(&g_lce[b & 1023], mx + logf(v) - l);
    }
}

// ------- split-bf16 HMMA GEMM + fused softmax-denominator epilogue -------
// sims = F @ C^T via 3 accumulating bf16 mma.sync terms; fp32 regs accumulate.
__global__ __launch_bounds__(256, 2)
void k_gemm(const float* __restrict__ F, const float* __restrict__ Cn,
            const int* __restrict__ labels) {
    extern __shared__ char smem_raw[];
    const uint32_t raw_u = smem_to_u32(smem_raw);
    const uint32_t sbase = (raw_u + 1023) & ~1023u;       // 1024-aligned
    char* tiles = smem_raw + (sbase - raw_u);

    const uint32_t AHI = sbase;
    const uint32_t ALO = sbase + TILE_B;
    const uint32_t BHI = sbase + 2 * TILE_B;
    const uint32_t BLO = sbase + 3 * TILE_B;

    const int tid  = threadIdx.x;
    const int wid  = tid >> 5;
    const int lane = tid & 31;
    const int warpm = wid & 3;          // 4 m-warps (32 rows each)
    const int warpn = wid >> 2;         // 2 n-warps (64 cols each)
    const int n0 = blockIdx.x * NT;
    const int m0 = blockIdx.y * MT;

    // loader mapping: g = 16B k-group (8 fp32), r0 = row block
    const int g  = tid & 7;
    const int r0 = tid >> 3;            // 0..31

    float acc[2][8][4];
    #pragma unroll
    for (int a = 0; a < 2; ++a)
        #pragma unroll
        for (int b = 0; b < 8; ++b)
            #pragma unroll
            for (int c = 0; c < 4; ++c) acc[a][b][c] = 0.f;

    for (int kt = 0; kt < NCHUNK; ++kt) {
        __syncthreads();   // previous MMA phase done before overwrite
        const int kb = kt * KC + g * 8;
        #pragma unroll
        for (int it = 0; it < 4; ++it) {
            const int r = r0 + it * 32;
            const uint32_t sw = SWZ128((uint32_t)(r * 128 + g * 16));
            // A (features)
            {
                const float* p = F + (size_t)(m0 + r) * FDIM + kb;
                float4 v0 = *(const float4*)p;
                float4 v1 = *(const float4*)(p + 4);
                float xs[8] = {v0.x, v0.y, v0.z, v0.w, v1.x, v1.y, v1.z, v1.w};
                uint32_t hw[4], lw[4];
                split8(xs, hw, lw);
                *(uint4*)(tiles + (AHI - sbase) + sw) = make_uint4(hw[0], hw[1], hw[2], hw[3]);
                *(uint4*)(tiles + (ALO - sbase) + sw) = make_uint4(lw[0], lw[1], lw[2], lw[3]);
            }
            // B (centers), zero-pad classes >= NCLS
            {
                const int c = n0 + r;
                float4 v0 = make_float4(0.f, 0.f, 0.f, 0.f), v1 = v0;
                if (c < NCLS) {
                    const float* p = Cn + (size_t)c * FDIM + kb;
                    v0 = *(const float4*)p;
                    v1 = *(const float4*)(p + 4);
                }
                float xs[8] = {v0.x, v0.y, v0.z, v0.w, v1.x, v1.y, v1.z, v1.w};
                uint32_t hw[4], lw[4];
                split8(xs, hw, lw);
                *(uint4*)(tiles + (BHI - sbase) + sw) = make_uint4(hw[0], hw[1], hw[2], hw[3]);
                *(uint4*)(tiles + (BLO - sbase) + sw) = make_uint4(lw[0], lw[1], lw[2], lw[3]);
            }
        }
        __syncthreads();

        // ---- MMA phase: 4 k-steps of 16 ----
        const int ar = lane & 15;          // A row within 16
        const int akh = lane >> 4;         // A k-half
        const int bidx = lane & 7;         // B n within 8
        const int bnh = (lane >> 4) & 1;   // B n-half
        const int bkh = (lane >> 3) & 1;   // B k-half
        #pragma unroll
        for (int ks = 0; ks < 4; ++ks) {
            uint32_t ahi[2][4], alo[2][4];
            #pragma unroll
            for (int mt = 0; mt < 2; ++mt) {
                const int row = warpm * 32 + mt * 16 + ar;
                const uint32_t off = SWZ128((uint32_t)(row * 128 + (ks * 2 + akh) * 16));
                ldsm4(ahi[mt], AHI + off);
                ldsm4(alo[mt], ALO + off);
            }
            #pragma unroll
            for (int ntp = 0; ntp < 4; ++ntp) {
                uint32_t bhi[4], blo[4];
                const int nloc = warpn * 64 + ntp * 16 + bnh * 8 + bidx;
                const uint32_t off = SWZ128((uint32_t)(nloc * 128 + (ks * 2 + bkh) * 16));
                ldsm4(bhi, BHI + off);
                ldsm4(blo, BLO + off);
                #pragma unroll
                for (int mt = 0; mt < 2; ++mt) {
                    #pragma unroll
                    for (int j = 0; j < 2; ++j) {
                        float* d = acc[mt][ntp * 2 + j];
                        mma_bf16(d, ahi[mt], &bhi[j * 2]);
                        mma_bf16(d, ahi[mt], &blo[j * 2]);
                        mma_bf16(d, alo[mt], &bhi[j * 2]);
                    }
                }
            }
        }
    }

    // ---- epilogue: per-row sum of exp(sims/T), capture label sim ----
    const int qrow = lane >> 2;
    const int qcol = lane & 3;
    #pragma unroll
    for (int mt = 0; mt < 2; ++mt) {
        #pragma unroll
        for (int half = 0; half < 2; ++half) {
            const int row = m0 + warpm * 32 + mt * 16 + half * 8 + qrow;
            const int lb = labels[row];
            float s = 0.f;
            #pragma unroll
            for (int nt = 0; nt < 8; ++nt) {
                #pragma unroll
                for (int j = 0; j < 2; ++j) {
                    const int c = n0 + warpn * 64 + nt * 8 + qcol * 2 + j;
                    const float v = acc[mt][nt][half * 2 + j];
                    if (c < NCLS) {
                        s += __expf(v * TEMP_INV);
                        if (c == lb) g_slabel[row] = v;
                    }
                }
            }
            s += __shfl_xor_sync(0xffffffffu, s, 1);
            s += __shfl_xor_sync(0xffffffffu, s, 2);
            if (qcol == 0) atomicAdd(&g_sumexp[row], s);
        }
    }
}

// ---------------- responsibility at label, wsum, SDC loss ----------------
__global__ void k_wsum(const int* __restrict__ labels) {
    int b = blockIdx.x * blockDim.x + threadIdx.x;
    if (b < B_ROWS) {
        float p = __expf(g_slabel[b] * TEMP_INV) / g_sumexp[b];
        g_w[b] = p;
        atomicAdd(&g_wsum[labels[b]], p);
        atomicAdd(&g_lsdc[b & 1023], -logf(p + EPSI));
    }
}

// ---------------- masked-weighted scatter ----------------
__global__ void k_scatter(const float* __restrict__ F, const int* __restrict__ labels) {
    const int b = blockIdx.x;
    const int lb = labels[b];
    const float coef = g_w[b] / (g_wsum[lb] + EPSI);
    float* dst = g_update + (size_t)lb * FDIM;
    const float* src = F + (size_t)b * FDIM;
    for (int d = threadIdx.x; d < FDIM; d += blockDim.x)
        atomicAdd(&dst[d], src[d] * coef);
}

// ---------------- loss finalize ----------------
__global__ void k_loss(float* __restrict__ d_out) {
    const int tid = threadIdx.x;  // 1024
    __shared__ float s1[32], s2[32];
    float v1 = g_lce[tid], v2 = g_lsdc[tid];
    #pragma unroll
    for (int o = 16; o; o >>= 1) {
        v1 += __shfl_xor_sync(0xffffffffu, v1, o);
        v2 += __shfl_xor_sync(0xffffffffu, v2, o);
    }
    if ((tid & 31) == 0) { s1[tid >> 5] = v1; s2[tid >> 5] = v2; }
    __syncthreads();
    if (tid < 32) {
        v1 = s1[tid]; v2 = s2[tid];
        #pragma unroll
        for (int o = 16; o; o >>= 1) {
            v1 += __shfl_xor_sync(0xffffffffu, v1, o);
            v2 += __shfl_xor_sync(0xffffffffu, v2, o);
        }
        if (tid == 0)
            d_out[0] = CE_W * v1 / (float)B_ROWS + SDC_W * v2 / (float)B_ROWS;
    }
}

// ---------------- centers finalize ----------------
__global__ void k_final(const float* __restrict__ centers, float* __restrict__ d_out) {
    int i = blockIdx.x * blockDim.x + threadIdx.x;
    if (i < NCLS * FDIM) {
        const int c = i / FDIM;
        const float w = g_wsum[c];
        d_out[1 + i] = (w > 0.f) ? (MOM * centers[i] + (1.f - MOM) * g_update[i])
                                 : centers[i];
    }
}

extern "C" void kernel_launch(void* const* d_in, const int* in_sizes, int n_in,
                              void* d_out, int out_size) {
    const float* outputs  = (const float*)d_in[0];
    const int*   labels   = (const int*)d_in[1];
    const float* features = (const float*)d_in[2];
    const float* centers  = (const float*)d_in[3];
    float* out = (float*)d_out;

    cudaFuncSetAttribute(k_gemm, cudaFuncAttributeMaxDynamicSharedMemorySize, SMEM_DYN);

    k_init<<<(NCLS * FDIM + 255) / 256, 256>>>();
    k_ce<<<B_ROWS, 256>>>(outputs, labels);
    {
        dim3 grid((NCLS + NT - 1) / NT, B_ROWS / MT);  // (8, 128): n-fast keeps A tile shared in L2
        k_gemm<<<grid, 256, SMEM_DYN>>>(features, centers, labels);
    }
    k_wsum<<<(B_ROWS + 255) / 256, 256>>>(labels);
    k_scatter<<<B_ROWS, 256>>>(features, labels);
    k_loss<<<1, 1024>>>(out);
    k_final<<<(NCLS * FDIM + 255) / 256, 256>>>(centers, out);
}

// round 5
// speedup vs baseline: 2.4806x; 1.0624x over previous
#include <cuda_runtime.h>
#include <cuda_bf16.h>
#include <cstdint>
#include <math.h>

// ---------------- problem constants ----------------
#define B_ROWS 16384
#define NCLS   1000
#define CPAD   1024                // padded class count (zero-filled)
#define FDIM   768
#define TEMP_INV 10.0f
#define CE_W   1.0f
#define SDC_W  0.1f
#define MOM    0.9f
#define EPSI   1e-8f

// ---------------- GEMM tiling ----------------
#define MT 128
#define NT 128
#define KC 64                      // k elems per chunk (64 bf16 = 128B row)
#define NCHUNK (FDIM / KC)         // 12
#define TILE_B 16384               // 128 rows x 128B
#define NSTAGE 3
#define STAGE_B (4 * TILE_B)       // Ahi Alo Bhi Blo = 64KB
#define SMEM_DYN (NSTAGE * STAGE_B + 1024)
#define GRID_N (CPAD / NT)         // 8

// ---------------- device scratch ----------------
__device__ float g_sumexp[B_ROWS];
__device__ float g_slabel[B_ROWS];
__device__ float g_w[B_ROWS];
__device__ float g_wsum[NCLS];
__device__ float g_update[NCLS * FDIM];
__device__ float g_lce[1024];
__device__ float g_lsdc[1024];

__device__ __align__(128) __nv_bfloat16 g_Fhi[B_ROWS * FDIM];
__device__ __align__(128) __nv_bfloat16 g_Flo[B_ROWS * FDIM];
__device__ __align__(128) __nv_bfloat16 g_Chi[CPAD * FDIM];
__device__ __align__(128) __nv_bfloat16 g_Clo[CPAD * FDIM];

// ---------------- helpers ----------------
__device__ __forceinline__ uint32_t smem_to_u32(const void* p) {
    uint32_t a;
    asm("{ .reg .u64 t; cvta.to.shared.u64 t, %1; cvt.u32.u64 %0, t; }" : "=r"(a) : "l"(p));
    return a;
}
#define SWZ128(off) ((off) ^ (((off) >> 3) & 0x70))

__device__ __forceinline__ void cp16(uint32_t dst, const void* src) {
    asm volatile("cp.async.cg.shared.global [%0], [%1], 16;" :: "r"(dst), "l"(src) : "memory");
}
#define CP_COMMIT() asm volatile("cp.async.commit_group;" ::: "memory")

__device__ __forceinline__ void ldsm4(uint32_t* r, uint32_t addr) {
    asm volatile("ldmatrix.sync.aligned.m8n8.x4.shared.b16 {%0,%1,%2,%3}, [%4];"
        : "=r"(r[0]), "=r"(r[1]), "=r"(r[2]), "=r"(r[3]) : "r"(addr));
}
__device__ __forceinline__ void mma_bf16(float* d, const uint32_t* a, const uint32_t* b) {
    asm volatile("mma.sync.aligned.m16n8k16.row.col.f32.bf16.bf16.f32 "
        "{%0,%1,%2,%3}, {%4,%5,%6,%7}, {%8,%9}, {%0,%1,%2,%3};"
        : "+f"(d[0]), "+f"(d[1]), "+f"(d[2]), "+f"(d[3])
        : "r"(a[0]), "r"(a[1]), "r"(a[2]), "r"(a[3]), "r"(b[0]), "r"(b[1]));
}

// split 8 fp32 -> 4 b32 packed bf16 hi + 4 lo
__device__ __forceinline__ void split8(const float* xs, uint32_t* hw, uint32_t* lw) {
    #pragma unroll
    for (int i = 0; i < 4; ++i) {
        __nv_bfloat16 h0 = __float2bfloat16_rn(xs[2*i]);
        __nv_bfloat16 h1 = __float2bfloat16_rn(xs[2*i+1]);
        __nv_bfloat16 l0 = __float2bfloat16_rn(xs[2*i]   - __bfloat162float(h0));
        __nv_bfloat16 l1 = __float2bfloat16_rn(xs[2*i+1] - __bfloat162float(h1));
        hw[i] = (uint32_t)__bfloat16_as_ushort(h0) | ((uint32_t)__bfloat16_as_ushort(h1) << 16);
        lw[i] = (uint32_t)__bfloat16_as_ushort(l0) | ((uint32_t)__bfloat16_as_ushort(l1) << 16);
    }
}

// ---------------- init ----------------
__global__ void k_init() {
    int i = blockIdx.x * blockDim.x + threadIdx.x;
    if (i < NCLS * FDIM) g_update[i] = 0.f;
    if (i < B_ROWS) g_sumexp[i] = 0.f;
    if (i < NCLS) g_wsum[i] = 0.f;
    if (i < 1024) { g_lce[i] = 0.f; g_lsdc[i] = 0.f; }
}

// ---------------- preconvert: fp32 -> bf16 hi/lo ----------------
__global__ __launch_bounds__(256) void k_convF(const float* __restrict__ F) {
    const size_t i = ((size_t)blockIdx.x * 256 + threadIdx.x) * 8;
    float4 v0 = *(const float4*)(F + i);
    float4 v1 = *(const float4*)(F + i + 4);
    float xs[8] = {v0.x, v0.y, v0.z, v0.w, v1.x, v1.y, v1.z, v1.w};
    uint32_t hw[4], lw[4];
    split8(xs, hw, lw);
    *(uint4*)(g_Fhi + i) = make_uint4(hw[0], hw[1], hw[2], hw[3]);
    *(uint4*)(g_Flo + i) = make_uint4(lw[0], lw[1], lw[2], lw[3]);
}

__global__ __launch_bounds__(256) void k_convC(const float* __restrict__ Cn) {
    const size_t i = ((size_t)blockIdx.x * 256 + threadIdx.x) * 8;
    const int row = (int)(i / FDIM);
    float xs[8] = {0.f, 0.f, 0.f, 0.f, 0.f, 0.f, 0.f, 0.f};
    if (row < NCLS) {
        float4 v0 = *(const float4*)(Cn + i);
        float4 v1 = *(const float4*)(Cn + i + 4);
        xs[0]=v0.x; xs[1]=v0.y; xs[2]=v0.z; xs[3]=v0.w;
        xs[4]=v1.x; xs[5]=v1.y; xs[6]=v1.z; xs[7]=v1.w;
    }
    uint32_t hw[4], lw[4];
    split8(xs, hw, lw);
    *(uint4*)(g_Chi + i) = make_uint4(hw[0], hw[1], hw[2], hw[3]);
    *(uint4*)(g_Clo + i) = make_uint4(lw[0], lw[1], lw[2], lw[3]);
}

// ---------------- CE loss: single-pass, register-resident row ----------------
__global__ __launch_bounds__(256) void k_ce(const float* __restrict__ out,
                                            const int* __restrict__ labels) {
    const int b = blockIdx.x;
    const float* row = out + (size_t)b * NCLS;
    const int tid = threadIdx.x;
    __shared__ float sh[32];
    __shared__ float shmx;

    float4 x = make_float4(-3.4e38f, -3.4e38f, -3.4e38f, -3.4e38f);
    const bool act = (tid < NCLS / 4);
    if (act) x = *(const float4*)(row + tid * 4);

    float mx = fmaxf(fmaxf(x.x, x.y), fmaxf(x.z, x.w));
    #pragma unroll
    for (int o = 16; o; o >>= 1) mx = fmaxf(mx, __shfl_xor_sync(0xffffffffu, mx, o));
    if ((tid & 31) == 0) sh[tid >> 5] = mx;
    __syncthreads();
    if (tid < 32) {
        float v = (tid < 8) ? sh[tid] : -3.4e38f;
        #pragma unroll
        for (int o = 4; o; o >>= 1) v = fmaxf(v, __shfl_xor_sync(0xffffffffu, v, o));
        if (tid == 0) shmx = v;
    }
    __syncthreads();
    mx = shmx;

    const int lb = labels[b];
    float s = 0.f, lval = 0.f;
    if (act) {
        s = __expf(x.x - mx) + __expf(x.y - mx) + __expf(x.z - mx) + __expf(x.w - mx);
        if (tid == (lb >> 2)) {
            const float* xe = &x.x;
            lval = xe[lb & 3];
        }
    }
    #pragma unroll
    for (int o = 16; o; o >>= 1) {
        s += __shfl_xor_sync(0xffffffffu, s, o);
        lval += __shfl_xor_sync(0xffffffffu, lval, o);
    }
    if ((tid & 31) == 0) { sh[tid >> 5] = s; sh[16 + (tid >> 5)] = lval; }
    __syncthreads();
    if (tid < 32) {
        float v = (tid < 8) ? sh[tid] : 0.f;
        float l = (tid < 8) ? sh[16 + tid] : 0.f;
        #pragma unroll
        for (int o = 4; o; o >>= 1) {
            v += __shfl_xor_sync(0xffffffffu, v, o);
            l += __shfl_xor_sync(0xffffffffu, l, o);
        }
        if (tid == 0) atomicAdd(&g_lce[b & 1023], mx + logf(v) - l);
    }
}

// ------- split-bf16 HMMA GEMM, cp.async 3-stage pipeline -------
__global__ __launch_bounds__(256, 1)
void k_gemm(const int* __restrict__ labels) {
    extern __shared__ char smem_raw[];
    const uint32_t raw_u = smem_to_u32(smem_raw);
    const uint32_t sbase = (raw_u + 1023) & ~1023u;

    const int tid  = threadIdx.x;
    const int wid  = tid >> 5;
    const int lane = tid & 31;
    const int warpm = wid & 3;
    const int warpn = wid >> 2;
    const int n0 = blockIdx.x * NT;
    const int m0 = blockIdx.y * MT;

    const int g  = tid & 7;
    const int r0 = tid >> 3;

    float acc[2][8][4];
    #pragma unroll
    for (int a = 0; a < 2; ++a)
        #pragma unroll
        for (int b = 0; b < 8; ++b)
            #pragma unroll
            for (int c = 0; c < 4; ++c) acc[a][b][c] = 0.f;

    auto issue = [&](int kt, int s) {
        const uint32_t sb = sbase + s * STAGE_B;
        const int kb = kt * KC + g * 8;
        #pragma unroll
        for (int it = 0; it < 4; ++it) {
            const int r = r0 + it * 32;
            const uint32_t sw = SWZ128((uint32_t)(r * 128 + g * 16));
            cp16(sb + sw,              g_Fhi + (size_t)(m0 + r) * FDIM + kb);
            cp16(sb + TILE_B + sw,     g_Flo + (size_t)(m0 + r) * FDIM + kb);
            cp16(sb + 2*TILE_B + sw,   g_Chi + (size_t)(n0 + r) * FDIM + kb);
            cp16(sb + 3*TILE_B + sw,   g_Clo + (size_t)(n0 + r) * FDIM + kb);
        }
        CP_COMMIT();
    };

    issue(0, 0);
    issue(1, 1);

    const int ar = lane & 15;
    const int akh = lane >> 4;
    const int bidx = lane & 7;
    const int bnh = (lane >> 4) & 1;
    const int bkh = (lane >> 3) & 1;

    for (int kt = 0; kt < NCHUNK; ++kt) {
        if (kt < NCHUNK - 1) asm volatile("cp.async.wait_group 1;" ::: "memory");
        else                 asm volatile("cp.async.wait_group 0;" ::: "memory");
        __syncthreads();

        const uint32_t sb = sbase + (kt % NSTAGE) * STAGE_B;
        const uint32_t AHI = sb, ALO = sb + TILE_B, BHI = sb + 2*TILE_B, BLO = sb + 3*TILE_B;

        #pragma unroll
        for (int ks = 0; ks < 4; ++ks) {
            uint32_t ahi[2][4], alo[2][4];
            #pragma unroll
            for (int mt = 0; mt < 2; ++mt) {
                const int row = warpm * 32 + mt * 16 + ar;
                const uint32_t off = SWZ128((uint32_t)(row * 128 + (ks * 2 + akh) * 16));
                ldsm4(ahi[mt], AHI + off);
                ldsm4(alo[mt], ALO + off);
            }
            #pragma unroll
            for (int ntp = 0; ntp < 4; ++ntp) {
                uint32_t bhi[4], blo[4];
                const int nloc = warpn * 64 + ntp * 16 + bnh * 8 + bidx;
                const uint32_t off = SWZ128((uint32_t)(nloc * 128 + (ks * 2 + bkh) * 16));
                ldsm4(bhi, BHI + off);
                ldsm4(blo, BLO + off);
                #pragma unroll
                for (int mt = 0; mt < 2; ++mt) {
                    #pragma unroll
                    for (int j = 0; j < 2; ++j) {
                        float* d = acc[mt][ntp * 2 + j];
                        mma_bf16(d, ahi[mt], &bhi[j * 2]);
                        mma_bf16(d, ahi[mt], &blo[j * 2]);
                        mma_bf16(d, alo[mt], &bhi[j * 2]);
                    }
                }
            }
        }
        __syncthreads();
        if (kt + 2 < NCHUNK) issue(kt + 2, (kt + 2) % NSTAGE);
    }

    // ---- epilogue: per-row sum of exp(sims/T), capture label sim ----
    const int qrow = lane >> 2;
    const int qcol = lane & 3;
    #pragma unroll
    for (int mt = 0; mt < 2; ++mt) {
        #pragma unroll
        for (int half = 0; half < 2; ++half) {
            const int row = m0 + warpm * 32 + mt * 16 + half * 8 + qrow;
            const int lb = labels[row];
            float s = 0.f;
            #pragma unroll
            for (int nt = 0; nt < 8; ++nt) {
                #pragma unroll
                for (int j = 0; j < 2; ++j) {
                    const int c = n0 + warpn * 64 + nt * 8 + qcol * 2 + j;
                    const float v = acc[mt][nt][half * 2 + j];
                    if (c < NCLS) {
                        s += __expf(v * TEMP_INV);
                        if (c == lb) g_slabel[row] = v;
                    }
                }
            }
            s += __shfl_xor_sync(0xffffffffu, s, 1);
            s += __shfl_xor_sync(0xffffffffu, s, 2);
            if (qcol == 0) atomicAdd(&g_sumexp[row], s);
        }
    }
}

// ---------------- responsibility at label, wsum, SDC loss ----------------
__global__ void k_wsum(const int* __restrict__ labels) {
    int b = blockIdx.x * blockDim.x + threadIdx.x;
    if (b < B_ROWS) {
        float p = __expf(g_slabel[b] * TEMP_INV) / g_sumexp[b];
        g_w[b] = p;
        atomicAdd(&g_wsum[labels[b]], p);
        atomicAdd(&g_lsdc[b & 1023], -logf(p + EPSI));
    }
}

// ---------------- masked-weighted scatter ----------------
__global__ void k_scatter(const float* __restrict__ F, const int* __restrict__ labels) {
    const int b = blockIdx.x;
    const int lb = labels[b];
    const float coef = g_w[b] / (g_wsum[lb] + EPSI);
    float* dst = g_update + (size_t)lb * FDIM;
    const float* src = F + (size_t)b * FDIM;
    for (int d = threadIdx.x; d < FDIM; d += blockDim.x)
        atomicAdd(&dst[d], src[d] * coef);
}

// ---------------- loss finalize ----------------
__global__ void k_loss(float* __restrict__ d_out) {
    const int tid = threadIdx.x;  // 1024
    __shared__ float s1[32], s2[32];
    float v1 = g_lce[tid], v2 = g_lsdc[tid];
    #pragma unroll
    for (int o = 16; o; o >>= 1) {
        v1 += __shfl_xor_sync(0xffffffffu, v1, o);
        v2 += __shfl_xor_sync(0xffffffffu, v2, o);
    }
    if ((tid & 31) == 0) { s1[tid >> 5] = v1; s2[tid >> 5] = v2; }
    __syncthreads();
    if (tid < 32) {
        v1 = s1[tid]; v2 = s2[tid];
        #pragma unroll
        for (int o = 16; o; o >>= 1) {
            v1 += __shfl_xor_sync(0xffffffffu, v1, o);
            v2 += __shfl_xor_sync(0xffffffffu, v2, o);
        }
        if (tid == 0)
            d_out[0] = CE_W * v1 / (float)B_ROWS + SDC_W * v2 / (float)B_ROWS;
    }
}

// ---------------- centers finalize ----------------
__global__ void k_final(const float* __restrict__ centers, float* __restrict__ d_out) {
    int i = blockIdx.x * blockDim.x + threadIdx.x;
    if (i < NCLS * FDIM) {
        const int c = i / FDIM;
        const float w = g_wsum[c];
        d_out[1 + i] = (w > 0.f) ? (MOM * centers[i] + (1.f - MOM) * g_update[i])
                                 : centers[i];
    }
}

extern "C" void kernel_launch(void* const* d_in, const int* in_sizes, int n_in,
                              void* d_out, int out_size) {
    const float* outputs  = (const float*)d_in[0];
    const int*   labels   = (const int*)d_in[1];
    const float* features = (const float*)d_in[2];
    const float* centers  = (const float*)d_in[3];
    float* out = (float*)d_out;

    cudaFuncSetAttribute(k_gemm, cudaFuncAttributeMaxDynamicSharedMemorySize, SMEM_DYN);

    k_init<<<(NCLS * FDIM + 255) / 256, 256>>>();
    k_convF<<<B_ROWS * FDIM / (256 * 8), 256>>>(features);
    k_convC<<<CPAD * FDIM / (256 * 8), 256>>>(centers);
    k_ce<<<B_ROWS, 256>>>(outputs, labels);
    {
        dim3 grid(GRID_N, B_ROWS / MT);   // (8, 128): n-fast keeps A tile shared in L2
        k_gemm<<<grid, 256, SMEM_DYN>>>(labels);
    }
    k_wsum<<<(B_ROWS + 255) / 256, 256>>>(labels);
    k_scatter<<<B_ROWS, 256>>>(features, labels);
    k_loss<<<1, 1024>>>(out);
    k_final<<<(NCLS * FDIM + 255) / 256, 256>>>(centers, out);
}

// round 6
// speedup vs baseline: 2.5541x; 1.0296x over previous
#include <cuda_runtime.h>
#include <cuda_bf16.h>
#include <cstdint>
#include <math.h>

// ---------------- problem constants ----------------
#define B_ROWS 16384
#define NCLS   1000
#define CPAD   1024                // padded class count (zero-filled)
#define FDIM   768
#define TEMP_INV 10.0f
#define CE_W   1.0f
#define SDC_W  0.1f
#define MOM    0.9f
#define EPSI   1e-8f

// ---------------- GEMM tiling ----------------
#define MT 128
#define NT 128
#define KC 64                      // k elems per chunk (64 bf16 = 128B row)
#define NCHUNK (FDIM / KC)         // 12
#define TILE_B 16384               // 128 rows x 128B
#define NSTAGE 3
#define STAGE_B (4 * TILE_B)       // Ahi Alo Bhi Blo = 64KB
#define SMEM_DYN (NSTAGE * STAGE_B + 1024)
#define GRID_N (CPAD / NT)         // 8

// ---------------- device scratch ----------------
__device__ float g_sumexp[B_ROWS];
__device__ float g_slabel[B_ROWS];
__device__ float g_w[B_ROWS];
__device__ float g_wsum[NCLS];
__device__ float g_update[NCLS * FDIM];
__device__ float g_lce[1024];
__device__ float g_lsdc[1024];

__device__ __align__(128) __nv_bfloat16 g_Fhi[B_ROWS * FDIM];
__device__ __align__(128) __nv_bfloat16 g_Flo[B_ROWS * FDIM];
__device__ __align__(128) __nv_bfloat16 g_Chi[CPAD * FDIM];
__device__ __align__(128) __nv_bfloat16 g_Clo[CPAD * FDIM];

// ---------------- helpers ----------------
__device__ __forceinline__ uint32_t smem_to_u32(const void* p) {
    uint32_t a;
    asm("{ .reg .u64 t; cvta.to.shared.u64 t, %1; cvt.u32.u64 %0, t; }" : "=r"(a) : "l"(p));
    return a;
}
#define SWZ128(off) ((off) ^ (((off) >> 3) & 0x70))

__device__ __forceinline__ void cp16(uint32_t dst, const void* src) {
    asm volatile("cp.async.cg.shared.global [%0], [%1], 16;" :: "r"(dst), "l"(src) : "memory");
}
#define CP_COMMIT() asm volatile("cp.async.commit_group;" ::: "memory")

__device__ __forceinline__ void ldsm4(uint32_t* r, uint32_t addr) {
    asm volatile("ldmatrix.sync.aligned.m8n8.x4.shared.b16 {%0,%1,%2,%3}, [%4];"
        : "=r"(r[0]), "=r"(r[1]), "=r"(r[2]), "=r"(r[3]) : "r"(addr));
}
__device__ __forceinline__ void mma_bf16(float* d, const uint32_t* a, const uint32_t* b) {
    asm volatile("mma.sync.aligned.m16n8k16.row.col.f32.bf16.bf16.f32 "
        "{%0,%1,%2,%3}, {%4,%5,%6,%7}, {%8,%9}, {%0,%1,%2,%3};"
        : "+f"(d[0]), "+f"(d[1]), "+f"(d[2]), "+f"(d[3])
        : "r"(a[0]), "r"(a[1]), "r"(a[2]), "r"(a[3]), "r"(b[0]), "r"(b[1]));
}

// split 8 fp32 -> 4 b32 packed bf16 hi + 4 lo
__device__ __forceinline__ void split8(const float* xs, uint32_t* hw, uint32_t* lw) {
    #pragma unroll
    for (int i = 0; i < 4; ++i) {
        __nv_bfloat16 h0 = __float2bfloat16_rn(xs[2*i]);
        __nv_bfloat16 h1 = __float2bfloat16_rn(xs[2*i+1]);
        __nv_bfloat16 l0 = __float2bfloat16_rn(xs[2*i]   - __bfloat162float(h0));
        __nv_bfloat16 l1 = __float2bfloat16_rn(xs[2*i+1] - __bfloat162float(h1));
        hw[i] = (uint32_t)__bfloat16_as_ushort(h0) | ((uint32_t)__bfloat16_as_ushort(h1) << 16);
        lw[i] = (uint32_t)__bfloat16_as_ushort(l0) | ((uint32_t)__bfloat16_as_ushort(l1) << 16);
    }
}

// ---------------- init ----------------
__global__ void k_init() {
    int i = blockIdx.x * blockDim.x + threadIdx.x;
    if (i < NCLS * FDIM) g_update[i] = 0.f;
    if (i < B_ROWS) g_sumexp[i] = 0.f;
    if (i < NCLS) g_wsum[i] = 0.f;
    if (i < 1024) { g_lce[i] = 0.f; g_lsdc[i] = 0.f; }
}

// ---------------- preconvert: fp32 -> bf16 hi/lo ----------------
__global__ __launch_bounds__(256) void k_convF(const float* __restrict__ F) {
    const size_t i = ((size_t)blockIdx.x * 256 + threadIdx.x) * 8;
    float4 v0 = *(const float4*)(F + i);
    float4 v1 = *(const float4*)(F + i + 4);
    float xs[8] = {v0.x, v0.y, v0.z, v0.w, v1.x, v1.y, v1.z, v1.w};
    uint32_t hw[4], lw[4];
    split8(xs, hw, lw);
    *(uint4*)(g_Fhi + i) = make_uint4(hw[0], hw[1], hw[2], hw[3]);
    *(uint4*)(g_Flo + i) = make_uint4(lw[0], lw[1], lw[2], lw[3]);
}

__global__ __launch_bounds__(256) void k_convC(const float* __restrict__ Cn) {
    const size_t i = ((size_t)blockIdx.x * 256 + threadIdx.x) * 8;
    const int row = (int)(i / FDIM);
    float xs[8] = {0.f, 0.f, 0.f, 0.f, 0.f, 0.f, 0.f, 0.f};
    if (row < NCLS) {
        float4 v0 = *(const float4*)(Cn + i);
        float4 v1 = *(const float4*)(Cn + i + 4);
        xs[0]=v0.x; xs[1]=v0.y; xs[2]=v0.z; xs[3]=v0.w;
        xs[4]=v1.x; xs[5]=v1.y; xs[6]=v1.z; xs[7]=v1.w;
    }
    uint32_t hw[4], lw[4];
    split8(xs, hw, lw);
    *(uint4*)(g_Chi + i) = make_uint4(hw[0], hw[1], hw[2], hw[3]);
    *(uint4*)(g_Clo + i) = make_uint4(lw[0], lw[1], lw[2], lw[3]);
}

// ---------------- CE loss: warp-per-row, register resident ----------------
__global__ __launch_bounds__(256) void k_ce(const float* __restrict__ out,
                                            const int* __restrict__ labels) {
    const int warp = threadIdx.x >> 5;
    const int lane = threadIdx.x & 31;
    const int b = blockIdx.x * 8 + warp;
    const float* row = out + (size_t)b * NCLS;

    float4 v[8];
    #pragma unroll
    for (int i = 0; i < 8; ++i) {
        const int idx = lane + 32 * i;      // float4 index, 250 valid
        v[i] = (idx < 250) ? *(const float4*)(row + idx * 4)
                           : make_float4(-3.4e38f, -3.4e38f, -3.4e38f, -3.4e38f);
    }

    float mx = -3.4e38f;
    #pragma unroll
    for (int i = 0; i < 8; ++i)
        mx = fmaxf(mx, fmaxf(fmaxf(v[i].x, v[i].y), fmaxf(v[i].z, v[i].w)));
    #pragma unroll
    for (int o = 16; o; o >>= 1) mx = fmaxf(mx, __shfl_xor_sync(0xffffffffu, mx, o));

    const int lb = labels[b];
    const int lidx = lb >> 2;
    float s = 0.f, lval = 0.f;
    #pragma unroll
    for (int i = 0; i < 8; ++i) {
        const int idx = lane + 32 * i;
        if (idx < 250) {
            s += __expf(v[i].x - mx) + __expf(v[i].y - mx)
               + __expf(v[i].z - mx) + __expf(v[i].w - mx);
            if (idx == lidx) {
                const float* e = &v[i].x;
                lval = e[lb & 3];
            }
        }
    }
    #pragma unroll
    for (int o = 16; o; o >>= 1) {
        s += __shfl_xor_sync(0xffffffffu, s, o);
        lval += __shfl_xor_sync(0xffffffffu, lval, o);
    }
    if (lane == 0) atomicAdd(&g_lce[b & 1023], mx + logf(s) - lval);
}

// ------- split-bf16 HMMA GEMM, cp.async 3-stage pipeline, term-outermost MMA -------
__global__ __launch_bounds__(256, 1)
void k_gemm(const int* __restrict__ labels) {
    extern __shared__ char smem_raw[];
    const uint32_t raw_u = smem_to_u32(smem_raw);
    const uint32_t sbase = (raw_u + 1023) & ~1023u;

    const int tid  = threadIdx.x;
    const int wid  = tid >> 5;
    const int lane = tid & 31;
    const int warpm = wid & 3;
    const int warpn = wid >> 2;
    const int n0 = blockIdx.x * NT;
    const int m0 = blockIdx.y * MT;

    const int g  = tid & 7;
    const int r0 = tid >> 3;

    float acc[2][8][4];
    #pragma unroll
    for (int a = 0; a < 2; ++a)
        #pragma unroll
        for (int b = 0; b < 8; ++b)
            #pragma unroll
            for (int c = 0; c < 4; ++c) acc[a][b][c] = 0.f;

    auto issue = [&](int kt, int s) {
        const uint32_t sb = sbase + s * STAGE_B;
        const int kb = kt * KC + g * 8;
        #pragma unroll
        for (int it = 0; it < 4; ++it) {
            const int r = r0 + it * 32;
            const uint32_t sw = SWZ128((uint32_t)(r * 128 + g * 16));
            cp16(sb + sw,              g_Fhi + (size_t)(m0 + r) * FDIM + kb);
            cp16(sb + TILE_B + sw,     g_Flo + (size_t)(m0 + r) * FDIM + kb);
            cp16(sb + 2*TILE_B + sw,   g_Chi + (size_t)(n0 + r) * FDIM + kb);
            cp16(sb + 3*TILE_B + sw,   g_Clo + (size_t)(n0 + r) * FDIM + kb);
        }
        CP_COMMIT();
    };

    issue(0, 0);
    issue(1, 1);

    const int ar = lane & 15;
    const int akh = lane >> 4;
    const int bidx = lane & 7;
    const int bnh = (lane >> 4) & 1;
    const int bkh = (lane >> 3) & 1;

    for (int kt = 0; kt < NCHUNK; ++kt) {
        if (kt < NCHUNK - 1) asm volatile("cp.async.wait_group 1;" ::: "memory");
        else                 asm volatile("cp.async.wait_group 0;" ::: "memory");
        __syncthreads();

        // safe to refill stage (kt+2)%3: all warps finished reading it at iter kt-1
        if (kt + 2 < NCHUNK) issue(kt + 2, (kt + 2) % NSTAGE);

        const uint32_t sb = sbase + (kt % NSTAGE) * STAGE_B;
        const uint32_t AHI = sb, ALO = sb + TILE_B, BHI = sb + 2*TILE_B, BLO = sb + 3*TILE_B;

        #pragma unroll
        for (int ks = 0; ks < 4; ++ks) {
            uint32_t ahi[2][4], alo[2][4], bhi[4][4], blo[4][4];
            #pragma unroll
            for (int mt = 0; mt < 2; ++mt) {
                const int row = warpm * 32 + mt * 16 + ar;
                const uint32_t off = SWZ128((uint32_t)(row * 128 + (ks * 2 + akh) * 16));
                ldsm4(ahi[mt], AHI + off);
                ldsm4(alo[mt], ALO + off);
            }
            #pragma unroll
            for (int ntp = 0; ntp < 4; ++ntp) {
                const int nloc = warpn * 64 + ntp * 16 + bnh * 8 + bidx;
                const uint32_t off = SWZ128((uint32_t)(nloc * 128 + (ks * 2 + bkh) * 16));
                ldsm4(bhi[ntp], BHI + off);
                ldsm4(blo[ntp], BLO + off);
            }
            // term 1: Ahi * Bhi — 16 independent accumulators back-to-back
            #pragma unroll
            for (int ntp = 0; ntp < 4; ++ntp)
                #pragma unroll
                for (int mt = 0; mt < 2; ++mt)
                    #pragma unroll
                    for (int j = 0; j < 2; ++j)
                        mma_bf16(acc[mt][ntp * 2 + j], ahi[mt], &bhi[ntp][j * 2]);
            // term 2: Ahi * Blo
            #pragma unroll
            for (int ntp = 0; ntp < 4; ++ntp)
                #pragma unroll
                for (int mt = 0; mt < 2; ++mt)
                    #pragma unroll
                    for (int j = 0; j < 2; ++j)
                        mma_bf16(acc[mt][ntp * 2 + j], ahi[mt], &blo[ntp][j * 2]);
            // term 3: Alo * Bhi
            #pragma unroll
            for (int ntp = 0; ntp < 4; ++ntp)
                #pragma unroll
                for (int mt = 0; mt < 2; ++mt)
                    #pragma unroll
                    for (int j = 0; j < 2; ++j)
                        mma_bf16(acc[mt][ntp * 2 + j], alo[mt], &bhi[ntp][j * 2]);
        }
    }

    // ---- epilogue: per-row sum of exp(sims/T), capture label sim ----
    const int qrow = lane >> 2;
    const int qcol = lane & 3;
    #pragma unroll
    for (int mt = 0; mt < 2; ++mt) {
        #pragma unroll
        for (int half = 0; half < 2; ++half) {
            const int row = m0 + warpm * 32 + mt * 16 + half * 8 + qrow;
            const int lb = labels[row];
            float s = 0.f;
            #pragma unroll
            for (int nt = 0; nt < 8; ++nt) {
                #pragma unroll
                for (int j = 0; j < 2; ++j) {
                    const int c = n0 + warpn * 64 + nt * 8 + qcol * 2 + j;
                    const float v = acc[mt][nt][half * 2 + j];
                    if (c < NCLS) {
                        s += __expf(v * TEMP_INV);
                        if (c == lb) g_slabel[row] = v;
                    }
                }
            }
            s += __shfl_xor_sync(0xffffffffu, s, 1);
            s += __shfl_xor_sync(0xffffffffu, s, 2);
            if (qcol == 0) atomicAdd(&g_sumexp[row], s);
        }
    }
}

// ---------------- responsibility at label, wsum, SDC loss ----------------
__global__ void k_wsum(const int* __restrict__ labels) {
    int b = blockIdx.x * blockDim.x + threadIdx.x;
    if (b < B_ROWS) {
        float p = __expf(g_slabel[b] * TEMP_INV) / g_sumexp[b];
        g_w[b] = p;
        atomicAdd(&g_wsum[labels[b]], p);
        atomicAdd(&g_lsdc[b & 1023], -logf(p + EPSI));
    }
}

// ---------------- masked-weighted scatter ----------------
__global__ void k_scatter(const float* __restrict__ F, const int* __restrict__ labels) {
    const int b = blockIdx.x;
    const int lb = labels[b];
    const float coef = g_w[b] / (g_wsum[lb] + EPSI);
    float* dst = g_update + (size_t)lb * FDIM;
    const float* src = F + (size_t)b * FDIM;
    for (int d = threadIdx.x; d < FDIM; d += blockDim.x)
        atomicAdd(&dst[d], src[d] * coef);
}

// ---------------- loss finalize ----------------
__global__ void k_loss(float* __restrict__ d_out) {
    const int tid = threadIdx.x;  // 1024
    __shared__ float s1[32], s2[32];
    float v1 = g_lce[tid], v2 = g_lsdc[tid];
    #pragma unroll
    for (int o = 16; o; o >>= 1) {
        v1 += __shfl_xor_sync(0xffffffffu, v1, o);
        v2 += __shfl_xor_sync(0xffffffffu, v2, o);
    }
    if ((tid & 31) == 0) { s1[tid >> 5] = v1; s2[tid >> 5] = v2; }
    __syncthreads();
    if (tid < 32) {
        v1 = s1[tid]; v2 = s2[tid];
        #pragma unroll
        for (int o = 16; o; o >>= 1) {
            v1 += __shfl_xor_sync(0xffffffffu, v1, o);
            v2 += __shfl_xor_sync(0xffffffffu, v2, o);
        }
        if (tid == 0)
            d_out[0] = CE_W * v1 / (float)B_ROWS + SDC_W * v2 / (float)B_ROWS;
    }
}

// ---------------- centers finalize ----------------
__global__ void k_final(const float* __restrict__ centers, float* __restrict__ d_out) {
    int i = blockIdx.x * blockDim.x + threadIdx.x;
    if (i < NCLS * FDIM) {
        const int c = i / FDIM;
        const float w = g_wsum[c];
        d_out[1 + i] = (w > 0.f) ? (MOM * centers[i] + (1.f - MOM) * g_update[i])
                                 : centers[i];
    }
}

extern "C" void kernel_launch(void* const* d_in, const int* in_sizes, int n_in,
                              void* d_out, int out_size) {
    const float* outputs  = (const float*)d_in[0];
    const int*   labels   = (const int*)d_in[1];
    const float* features = (const float*)d_in[2];
    const float* centers  = (const float*)d_in[3];
    float* out = (float*)d_out;

    cudaFuncSetAttribute(k_gemm, cudaFuncAttributeMaxDynamicSharedMemorySize, SMEM_DYN);

    k_init<<<(NCLS * FDIM + 255) / 256, 256>>>();
    k_convF<<<B_ROWS * FDIM / (256 * 8), 256>>>(features);
    k_convC<<<CPAD * FDIM / (256 * 8), 256>>>(centers);
    k_ce<<<B_ROWS / 8, 256>>>(outputs, labels);
    {
        dim3 grid(GRID_N, B_ROWS / MT);   // (8, 128)
        k_gemm<<<grid, 256, SMEM_DYN>>>(labels);
    }
    k_wsum<<<(B_ROWS + 255) / 256, 256>>>(labels);
    k_scatter<<<B_ROWS, 256>>>(features, labels);
    k_loss<<<1, 1024>>>(out);
    k_final<<<(NCLS * FDIM + 255) / 256, 256>>>(centers, out);
}